// round 15
// baseline (speedup 1.0000x reference)
#include <cuda_runtime.h>
#include <math.h>

#define B_   16
#define N_   2048
#define K_   16
#define EPS_ 1e-8f

// Output layout (tuple flattened in order):
//   psi_prime : B*N*2  floats  @ 0
//   features  : B*N*5  floats  @ 65536
//   knn_idx   : B*N*16 floats  @ 229376
#define PSI_OFF  0
#define FEAT_OFF (B_ * N_ * 2)
#define KNN_OFF  (B_ * N_ * 2 + B_ * N_ * 5)

typedef unsigned long long u64;
typedef unsigned int u32;

#define SENT 0xFFFFFFFFFFFFFFFFull
#define SUB_ (N_ / 2)          // candidates per thread (2 threads/query)
#define NIT  (SUB_ / 16)       // 16-candidate iterations per thread (64)

// SOA candidate data for the KNN kernel.
__device__ float g_x [B_ * N_];
__device__ float g_y [B_ * N_];
__device__ float g_sq[B_ * N_];

// ---------------------------------------------------------------------------
// Kernel 1: features + encoder (tiny MLP) + SOA coord scratch.
// ---------------------------------------------------------------------------
__global__ void encode_kernel(const float* __restrict__ coords,
                              const float* __restrict__ demands,
                              const float* __restrict__ capacity,
                              const float* __restrict__ Wa,
                              const float* __restrict__ ba,
                              const float* __restrict__ W1,
                              const float* __restrict__ b1,
                              const float* __restrict__ W2,
                              const float* __restrict__ b2,
                              float* __restrict__ out)
{
    int b = blockIdx.y;
    int n = blockIdx.x * blockDim.x + threadIdx.x;
    if (n >= N_) return;

    __shared__ float sWa[10], sba[2], sW1[80], sb1[16], sW2[16], sb2_s;
    int t = threadIdx.x;
    if (t < 10) sWa[t] = Wa[t];
    if (t < 2)  sba[t] = ba[t];
    if (t < 80) sW1[t] = W1[t];
    if (t < 16) { sb1[t] = b1[t]; sW2[t] = W2[t]; }
    if (t == 0) sb2_s = b2[0];
    __syncthreads();

    const float* cp = coords + ((long long)b * N_ + n) * 2;
    float x = cp[0], y = cp[1];

    // SOA scratch for knn; sq = rn(rn(x*x) + rn(y*y)) (reference rounding)
    float sq = __fadd_rn(__fmul_rn(x, x), __fmul_rn(y, y));
    g_x [b * N_ + n] = x;
    g_y [b * N_ + n] = y;
    g_sq[b * N_ + n] = sq;

    float dx0 = coords[(long long)b * N_ * 2 + 0];
    float dy0 = coords[(long long)b * N_ * 2 + 1];
    float rx = x - dx0, ry = y - dy0;
    float dist = sqrtf(rx * rx + ry * ry + EPS_);
    float ang  = atan2f(ry, rx);
    float dem  = demands[(long long)b * N_ + n] / capacity[b];

    float f0 = x, f1 = y, f2 = dem, f3 = dist, f4 = ang;

    float* fo = out + FEAT_OFF + ((long long)b * N_ + n) * 5;
    fo[0] = f0; fo[1] = f1; fo[2] = f2; fo[3] = f3; fo[4] = f4;

    float p0 = sba[0] + f0*sWa[0] + f1*sWa[1] + f2*sWa[2] + f3*sWa[3] + f4*sWa[4];
    float p1 = sba[1] + f0*sWa[5] + f1*sWa[6] + f2*sWa[7] + f3*sWa[8] + f4*sWa[9];
    float nrm = sqrtf(p0 * p0 + p1 * p1);
    float inv = 1.0f / (nrm + EPS_);
    p0 *= inv; p1 *= inv;

    float theta = sb2_s;
    #pragma unroll
    for (int h = 0; h < 16; ++h) {
        const float* w = sW1 + h * 5;
        float a = sb1[h] + f0*w[0] + f1*w[1] + f2*w[2] + f3*w[3] + f4*w[4];
        theta += tanhf(a) * sW2[h];
    }
    float c = cosf(theta), s = sinf(theta);

    float* po = out + PSI_OFF + ((long long)b * N_ + n) * 2;
    po[0] = c * p0 - s * p1;
    po[1] = s * p0 + c * p1;
}

// ---------------------------------------------------------------------------
// KNN helpers
// ---------------------------------------------------------------------------

// Monotone map: float bits -> u32 whose unsigned order == float order.
__device__ __forceinline__ u32 fmap(u32 b) {
    return b ^ ((u32)((int)b >> 31) | 0x80000000u);
}

// Flush: convert raw (f32bits<<32|j) buffer entries to total-order keys,
// bitonic-sort-16, merge into sorted L (min-pair + clean), tighten tau.
// Exact ties: keys are (fmap(d2), j) lexicographic. (R7/R10-proven.)
__device__ __forceinline__ void flush16(u64* L, const u64* lbuf, int& n,
                                        float& tau_f)
{
    u64 s[16];
    #pragma unroll
    for (int i = 0; i < 16; ++i) {
        u64 raw = lbuf[i];
        u64 key = ((u64)fmap((u32)(raw >> 32)) << 32) | (u32)raw;
        s[i] = (i < n) ? key : SENT;
    }

    // Bitonic sort 16, ascending.
    #pragma unroll
    for (int k = 2; k <= 16; k <<= 1) {
        #pragma unroll
        for (int j = k >> 1; j > 0; j >>= 1) {
            #pragma unroll
            for (int i = 0; i < 16; ++i) {
                int l = i ^ j;
                if (l > i) {
                    bool up = ((i & k) == 0);
                    u64 a = s[i], b = s[l];
                    bool sw = up ? (a > b) : (a < b);
                    s[i] = sw ? b : a;
                    s[l] = sw ? a : b;
                }
            }
        }
    }

    // Lowest 16 of (L asc, s asc): min-pair -> bitonic, then clean.
    #pragma unroll
    for (int i = 0; i < 16; ++i) {
        u64 a = L[i], b = s[15 - i];
        L[i] = (a < b) ? a : b;
    }
    #pragma unroll
    for (int j = 8; j > 0; j >>= 1) {
        #pragma unroll
        for (int i = 0; i < 16; ++i) {
            int l = i ^ j;
            if (l > i) {
                u64 a = L[i], b = L[l];
                bool sw = a > b;
                L[i] = sw ? b : a;
                L[l] = sw ? a : b;
            }
        }
    }

    // tau = d2 of current 16th (inverse fmap). If L[15] is SENT this
    // decodes NaN; the fminf in the tau-share step then takes the
    // partner's value (fminf(NaN, x) = x). First flush fires with every
    // lane at n=16 (tau=inf until then), so L is full when tau matters.
    u32 h = (u32)(L[15] >> 32);
    h = (h & 0x80000000u) ? (h ^ 0x80000000u) : ~h;
    tau_f = __uint_as_float(h);
    n = 0;
}

// d2 bit-exact with the reference:
//   t = rn(xq*xj); dot = fma(yq,yj,t); s = rn(sqq+sqj)
//   ref rn(s - rn(2*dot)) == rn(s - 2*dot) == fma(-2, dot, s)   [2*dot exact]
#define D2_OF(xv, yv, sv) \
    __fmaf_rn(-2.0f, __fmaf_rn(yq, (yv), __fmul_rn(xq, (xv))), \
              __fadd_rn(sqq, (sv)))

// Branchless append: unconditionally write slot n (garbage beyond n is
// masked by the flush's i<n guard), conditionally advance n. No branches,
// no BSSY/BSYNC; overflow-safe (n<=8 at group entry -> max write index 15).
// '<=' so equal-d2/smaller-j candidates always enter; the u64-key flush
// resolves ties exactly (top_k stable order).
#define APPEND(ev, jv)                                               \
    do {                                                             \
        lbuf[n] = ((u64)__float_as_uint(ev) << 32) | (u32)(jv);      \
        n += (int)((ev) <= tau_f);                                   \
    } while (0)

// ---------------------------------------------------------------------------
// Kernel 2: KNN top-16, buffered deferred selection, 2 threads per query.
// R10 (129.7us) semantics with two hot-loop-only changes:
//  (a) branchless predicate-free appends (see APPEND above)
//  (b) 16-candidate iterations: 12 batched LDG.128, 16 d2, two 8-append
//      groups each followed by the ballot check (invariant n<=8 preserved;
//      first flush still fires with all lanes at n=16).
// Flush, tau-share, drain, partner merge: byte-identical to R10.
// ---------------------------------------------------------------------------
__global__ void __launch_bounds__(128)
knn_kernel(float* __restrict__ out_knn)
{
    int qid = blockIdx.x * 64 + (threadIdx.x >> 1);  // global query id
    int p   = threadIdx.x & 1;                       // candidate-half
    int b   = qid >> 11;
    int q   = qid & (N_ - 1);

    const float* bx = g_x  + b * N_;
    const float* by = g_y  + b * N_;
    const float* bs = g_sq + b * N_;

    float xq  = __ldg(&bx[q]);
    float yq  = __ldg(&by[q]);
    float sqq = __ldg(&bs[q]);

    const float4* x4 = (const float4*)(bx + p * SUB_);
    const float4* y4 = (const float4*)(by + p * SUB_);
    const float4* s4 = (const float4*)(bs + p * SUB_);
    int jbase = p * SUB_;

    u64 L[16];
    #pragma unroll
    for (int k = 0; k < 16; ++k) L[k] = SENT;

    u64 lbuf[16];
    int n = 0;
    float tau_f = 3.4e38f;

    for (int i = 0; i < NIT; ++i) {
        float4 xa = __ldg(&x4[4 * i]);
        float4 xb = __ldg(&x4[4 * i + 1]);
        float4 xc = __ldg(&x4[4 * i + 2]);
        float4 xd = __ldg(&x4[4 * i + 3]);
        float4 ya = __ldg(&y4[4 * i]);
        float4 yb = __ldg(&y4[4 * i + 1]);
        float4 yc = __ldg(&y4[4 * i + 2]);
        float4 yd = __ldg(&y4[4 * i + 3]);
        float4 sa = __ldg(&s4[4 * i]);
        float4 sb = __ldg(&s4[4 * i + 1]);
        float4 sc = __ldg(&s4[4 * i + 2]);
        float4 sd = __ldg(&s4[4 * i + 3]);

        float e0  = D2_OF(xa.x, ya.x, sa.x);
        float e1  = D2_OF(xa.y, ya.y, sa.y);
        float e2  = D2_OF(xa.z, ya.z, sa.z);
        float e3  = D2_OF(xa.w, ya.w, sa.w);
        float e4  = D2_OF(xb.x, yb.x, sb.x);
        float e5  = D2_OF(xb.y, yb.y, sb.y);
        float e6  = D2_OF(xb.z, yb.z, sb.z);
        float e7  = D2_OF(xb.w, yb.w, sb.w);
        float e8  = D2_OF(xc.x, yc.x, sc.x);
        float e9  = D2_OF(xc.y, yc.y, sc.y);
        float e10 = D2_OF(xc.z, yc.z, sc.z);
        float e11 = D2_OF(xc.w, yc.w, sc.w);
        float e12 = D2_OF(xd.x, yd.x, sd.x);
        float e13 = D2_OF(xd.y, yd.y, sd.y);
        float e14 = D2_OF(xd.z, yd.z, sd.z);
        float e15 = D2_OF(xd.w, yd.w, sd.w);

        int j0 = jbase + 16 * i;
        // self-exclusion, one rare branch per 16-candidate iteration
        if ((unsigned)(q - j0) < 16u) {
            int r = q - j0;
            if (r == 0)  e0  = 2.0e30f;  if (r == 1)  e1  = 2.0e30f;
            if (r == 2)  e2  = 2.0e30f;  if (r == 3)  e3  = 2.0e30f;
            if (r == 4)  e4  = 2.0e30f;  if (r == 5)  e5  = 2.0e30f;
            if (r == 6)  e6  = 2.0e30f;  if (r == 7)  e7  = 2.0e30f;
            if (r == 8)  e8  = 2.0e30f;  if (r == 9)  e9  = 2.0e30f;
            if (r == 10) e10 = 2.0e30f;  if (r == 11) e11 = 2.0e30f;
            if (r == 12) e12 = 2.0e30f;  if (r == 13) e13 = 2.0e30f;
            if (r == 14) e14 = 2.0e30f;  if (r == 15) e15 = 2.0e30f;
        }

        // group 1 (candidates j0..j0+7), then buffer check
        APPEND(e0, j0);      APPEND(e1, j0 + 1);
        APPEND(e2, j0 + 2);  APPEND(e3, j0 + 3);
        APPEND(e4, j0 + 4);  APPEND(e5, j0 + 5);
        APPEND(e6, j0 + 6);  APPEND(e7, j0 + 7);
        if (__ballot_sync(0xffffffffu, n >= 9)) {
            flush16(L, lbuf, n, tau_f);
            tau_f = fminf(tau_f, __shfl_xor_sync(0xffffffffu, tau_f, 1));
        }

        // group 2 (candidates j0+8..j0+15), then buffer check
        APPEND(e8, j0 + 8);   APPEND(e9, j0 + 9);
        APPEND(e10, j0 + 10); APPEND(e11, j0 + 11);
        APPEND(e12, j0 + 12); APPEND(e13, j0 + 13);
        APPEND(e14, j0 + 14); APPEND(e15, j0 + 15);
        if (__ballot_sync(0xffffffffu, n >= 9)) {
            flush16(L, lbuf, n, tau_f);
            tau_f = fminf(tau_f, __shfl_xor_sync(0xffffffffu, tau_f, 1));
        }
    }

    flush16(L, lbuf, n, tau_f);   // drain

    // Merge partner halves (lane^1): min-pair vs partner's reversed sorted
    // list -> bitonic -> clean. Both lanes end with the identical top-16.
    #pragma unroll
    for (int i = 0; i < 16; ++i) {
        u64 other = __shfl_xor_sync(0xffffffffu, L[15 - i], 1);
        u64 a = L[i];
        L[i] = (a < other) ? a : other;
    }
    #pragma unroll
    for (int j = 8; j > 0; j >>= 1) {
        #pragma unroll
        for (int i = 0; i < 16; ++i) {
            int l = i ^ j;
            if (l > i) {
                u64 a = L[i], b2 = L[l];
                bool sw = a > b2;
                L[i] = sw ? b2 : a;
                L[l] = sw ? a : b2;
            }
        }
    }

    // Each partner lane writes half the 16 outputs.
    float* o = out_knn + ((long long)b * N_ + q) * K_;
    #pragma unroll
    for (int k = 0; k < 8; ++k) {
        int kk = p * 8 + k;
        o[kk] = (float)(u32)(L[kk] & 0xFFFFFFFFu);
    }
}

// ---------------------------------------------------------------------------
extern "C" void kernel_launch(void* const* d_in, const int* in_sizes, int n_in,
                              void* d_out, int out_size)
{
    const float* coords   = (const float*)d_in[0];
    const float* demands  = (const float*)d_in[1];
    const float* capacity = (const float*)d_in[2];
    const float* Wa       = (const float*)d_in[3];
    const float* ba       = (const float*)d_in[4];
    const float* W1       = (const float*)d_in[5];
    const float* b1       = (const float*)d_in[6];
    const float* W2       = (const float*)d_in[7];
    const float* b2       = (const float*)d_in[8];
    float* out = (float*)d_out;

    encode_kernel<<<dim3(N_ / 256, B_), 256>>>(coords, demands, capacity,
                                               Wa, ba, W1, b1, W2, b2, out);
    // B*N queries x 2 threads each; 128-thread blocks (64 queries/block)
    knn_kernel<<<dim3(B_ * N_ * 2 / 128), 128>>>(out + KNN_OFF);
}

// round 16
// speedup vs baseline: 2.7750x; 2.7750x over previous
#include <cuda_runtime.h>
#include <math.h>

#define B_   16
#define N_   2048
#define K_   16
#define EPS_ 1e-8f

// Output layout (tuple flattened in order):
//   psi_prime : B*N*2  floats  @ 0
//   features  : B*N*5  floats  @ 65536
//   knn_idx   : B*N*16 floats  @ 229376
#define PSI_OFF  0
#define FEAT_OFF (B_ * N_ * 2)
#define KNN_OFF  (B_ * N_ * 2 + B_ * N_ * 5)

typedef unsigned long long u64;
typedef unsigned int u32;

#define SENT 0xFFFFFFFFFFFFFFFFull
#define SUB_ (N_ / 2)          // candidates per thread (2 threads/query)
#define NWIN (SUB_ / 8)        // 8-candidate windows per thread (128)

// SOA candidate data for the KNN kernel.
__device__ float g_x [B_ * N_];
__device__ float g_y [B_ * N_];
__device__ float g_sq[B_ * N_];

// ---------------------------------------------------------------------------
// Kernel 1: features + encoder (tiny MLP) + SOA coord scratch.
// ---------------------------------------------------------------------------
__global__ void encode_kernel(const float* __restrict__ coords,
                              const float* __restrict__ demands,
                              const float* __restrict__ capacity,
                              const float* __restrict__ Wa,
                              const float* __restrict__ ba,
                              const float* __restrict__ W1,
                              const float* __restrict__ b1,
                              const float* __restrict__ W2,
                              const float* __restrict__ b2,
                              float* __restrict__ out)
{
    int b = blockIdx.y;
    int n = blockIdx.x * blockDim.x + threadIdx.x;
    if (n >= N_) return;

    __shared__ float sWa[10], sba[2], sW1[80], sb1[16], sW2[16], sb2_s;
    int t = threadIdx.x;
    if (t < 10) sWa[t] = Wa[t];
    if (t < 2)  sba[t] = ba[t];
    if (t < 80) sW1[t] = W1[t];
    if (t < 16) { sb1[t] = b1[t]; sW2[t] = W2[t]; }
    if (t == 0) sb2_s = b2[0];
    __syncthreads();

    const float* cp = coords + ((long long)b * N_ + n) * 2;
    float x = cp[0], y = cp[1];

    // SOA scratch for knn; sq = rn(rn(x*x) + rn(y*y)) (reference rounding)
    float sq = __fadd_rn(__fmul_rn(x, x), __fmul_rn(y, y));
    g_x [b * N_ + n] = x;
    g_y [b * N_ + n] = y;
    g_sq[b * N_ + n] = sq;

    float dx0 = coords[(long long)b * N_ * 2 + 0];
    float dy0 = coords[(long long)b * N_ * 2 + 1];
    float rx = x - dx0, ry = y - dy0;
    float dist = sqrtf(rx * rx + ry * ry + EPS_);
    float ang  = atan2f(ry, rx);
    float dem  = demands[(long long)b * N_ + n] / capacity[b];

    float f0 = x, f1 = y, f2 = dem, f3 = dist, f4 = ang;

    float* fo = out + FEAT_OFF + ((long long)b * N_ + n) * 5;
    fo[0] = f0; fo[1] = f1; fo[2] = f2; fo[3] = f3; fo[4] = f4;

    float p0 = sba[0] + f0*sWa[0] + f1*sWa[1] + f2*sWa[2] + f3*sWa[3] + f4*sWa[4];
    float p1 = sba[1] + f0*sWa[5] + f1*sWa[6] + f2*sWa[7] + f3*sWa[8] + f4*sWa[9];
    float nrm = sqrtf(p0 * p0 + p1 * p1);
    float inv = 1.0f / (nrm + EPS_);
    p0 *= inv; p1 *= inv;

    float theta = sb2_s;
    #pragma unroll
    for (int h = 0; h < 16; ++h) {
        const float* w = sW1 + h * 5;
        float a = sb1[h] + f0*w[0] + f1*w[1] + f2*w[2] + f3*w[3] + f4*w[4];
        theta += tanhf(a) * sW2[h];
    }
    float c = cosf(theta), s = sinf(theta);

    float* po = out + PSI_OFF + ((long long)b * N_ + n) * 2;
    po[0] = c * p0 - s * p1;
    po[1] = s * p0 + c * p1;
}

// ---------------------------------------------------------------------------
// KNN helpers
// ---------------------------------------------------------------------------

// Monotone map: float bits -> u32 whose unsigned order == float order.
__device__ __forceinline__ u32 fmap(u32 b) {
    return b ^ ((u32)((int)b >> 31) | 0x80000000u);
}

// Flush: convert raw (f32bits<<32|j) buffer entries to total-order keys,
// bitonic-sort-16, merge into sorted L (min-pair + clean), tighten tau.
// Exact ties: keys are (fmap(d2), j) lexicographic. (R7/R10-proven.)
__device__ __forceinline__ void flush16(u64* L, const u64* lbuf, int& n,
                                        float& tau_f)
{
    u64 s[16];
    #pragma unroll
    for (int i = 0; i < 16; ++i) {
        u64 raw = lbuf[i];
        u64 key = ((u64)fmap((u32)(raw >> 32)) << 32) | (u32)raw;
        s[i] = (i < n) ? key : SENT;
    }

    // Bitonic sort 16, ascending.
    #pragma unroll
    for (int k = 2; k <= 16; k <<= 1) {
        #pragma unroll
        for (int j = k >> 1; j > 0; j >>= 1) {
            #pragma unroll
            for (int i = 0; i < 16; ++i) {
                int l = i ^ j;
                if (l > i) {
                    bool up = ((i & k) == 0);
                    u64 a = s[i], b = s[l];
                    bool sw = up ? (a > b) : (a < b);
                    s[i] = sw ? b : a;
                    s[l] = sw ? a : b;
                }
            }
        }
    }

    // Lowest 16 of (L asc, s asc): min-pair -> bitonic, then clean.
    #pragma unroll
    for (int i = 0; i < 16; ++i) {
        u64 a = L[i], b = s[15 - i];
        L[i] = (a < b) ? a : b;
    }
    #pragma unroll
    for (int j = 8; j > 0; j >>= 1) {
        #pragma unroll
        for (int i = 0; i < 16; ++i) {
            int l = i ^ j;
            if (l > i) {
                u64 a = L[i], b = L[l];
                bool sw = a > b;
                L[i] = sw ? b : a;
                L[l] = sw ? a : b;
            }
        }
    }

    // tau = d2 of current 16th (inverse fmap). If L[15] is SENT this
    // decodes NaN; the fminf in the tau-share step then takes the
    // partner's value (fminf(NaN, x) = x). First flush fires with every
    // lane at n=16 (tau=inf until then), so L is full when tau matters.
    u32 h = (u32)(L[15] >> 32);
    h = (h & 0x80000000u) ? (h ^ 0x80000000u) : ~h;
    tau_f = __uint_as_float(h);
    n = 0;
}

// d2 bit-exact with the reference:
//   t = rn(xq*xj); dot = fma(yq,yj,t); s = rn(sqq+sqj)
//   ref rn(s - rn(2*dot)) == rn(s - 2*dot) == fma(-2, dot, s)   [2*dot exact]
#define D2_OF(xv, yv, sv) \
    __fmaf_rn(-2.0f, __fmaf_rn(yq, (yv), __fmul_rn(xq, (xv))), \
              __fadd_rn(sqq, (sv)))

#define KEY_OF(ev, jv) (((u64)__float_as_uint(ev) << 32) | (u32)(jv))

// ---------------------------------------------------------------------------
// Kernel 2: KNN top-16, buffered deferred selection, 2 threads per query.
// Identical to R10 (129.7us) except the append sites: instead of 8 branchy
// if(e<=tau){lbuf[n++]=key;} sites (BSSY/BSYNC/BRA per site, warp-coupled),
// the 8 predicates are computed up front, prefix-summed into slot indices,
// and each store is a lone single-statement conditional -> a predicated
// @P STL.64: no reconvergence overhead, and predicated-off lanes generate
// NO memory transaction (avoiding the R15 LSU flood). Same accept set, same
// buffer contents in the same order -> selection semantics unchanged.
// ---------------------------------------------------------------------------
__global__ void __launch_bounds__(128)
knn_kernel(float* __restrict__ out_knn)
{
    int qid = blockIdx.x * 64 + (threadIdx.x >> 1);  // global query id
    int p   = threadIdx.x & 1;                       // candidate-half
    int b   = qid >> 11;
    int q   = qid & (N_ - 1);

    const float* bx = g_x  + b * N_;
    const float* by = g_y  + b * N_;
    const float* bs = g_sq + b * N_;

    float xq  = __ldg(&bx[q]);
    float yq  = __ldg(&by[q]);
    float sqq = __ldg(&bs[q]);

    const float4* x4 = (const float4*)(bx + p * SUB_);
    const float4* y4 = (const float4*)(by + p * SUB_);
    const float4* s4 = (const float4*)(bs + p * SUB_);
    int jbase = p * SUB_;

    u64 L[16];
    #pragma unroll
    for (int k = 0; k < 16; ++k) L[k] = SENT;

    u64 lbuf[16];
    int n = 0;
    float tau_f = 3.4e38f;

    for (int i = 0; i < NWIN; ++i) {
        float4 xa = __ldg(&x4[2 * i]);
        float4 xb = __ldg(&x4[2 * i + 1]);
        float4 ya = __ldg(&y4[2 * i]);
        float4 yb = __ldg(&y4[2 * i + 1]);
        float4 sa = __ldg(&s4[2 * i]);
        float4 sb = __ldg(&s4[2 * i + 1]);

        float e0 = D2_OF(xa.x, ya.x, sa.x);
        float e1 = D2_OF(xa.y, ya.y, sa.y);
        float e2 = D2_OF(xa.z, ya.z, sa.z);
        float e3 = D2_OF(xa.w, ya.w, sa.w);
        float e4 = D2_OF(xb.x, yb.x, sb.x);
        float e5 = D2_OF(xb.y, yb.y, sb.y);
        float e6 = D2_OF(xb.z, yb.z, sb.z);
        float e7 = D2_OF(xb.w, yb.w, sb.w);

        int j0 = jbase + 8 * i;
        // self-exclusion, one rare branch per 8-window
        if ((unsigned)(q - j0) < 8u) {
            int r = q - j0;
            if (r == 0) e0 = 2.0e30f;  if (r == 1) e1 = 2.0e30f;
            if (r == 2) e2 = 2.0e30f;  if (r == 3) e3 = 2.0e30f;
            if (r == 4) e4 = 2.0e30f;  if (r == 5) e5 = 2.0e30f;
            if (r == 6) e6 = 2.0e30f;  if (r == 7) e7 = 2.0e30f;
        }

        // Prefix-computed predicated appends. '<=' so equal-d2/smaller-j
        // candidates always enter; the u64-key flush resolves ties exactly
        // (top_k stable order). n <= 8 at entry -> slots <= 15: no overflow.
        {
            bool p0 = (e0 <= tau_f), p1 = (e1 <= tau_f);
            bool p2 = (e2 <= tau_f), p3 = (e3 <= tau_f);
            bool p4 = (e4 <= tau_f), p5 = (e5 <= tau_f);
            bool p6 = (e6 <= tau_f), p7 = (e7 <= tau_f);
            int s0 = n;
            int s1 = s0 + p0;
            int s2 = s1 + p1;
            int s3 = s2 + p2;
            int s4_ = s3 + p3;
            int s5 = s4_ + p4;
            int s6 = s5 + p5;
            int s7 = s6 + p6;
            if (p0) lbuf[s0]  = KEY_OF(e0, j0);
            if (p1) lbuf[s1]  = KEY_OF(e1, j0 + 1);
            if (p2) lbuf[s2]  = KEY_OF(e2, j0 + 2);
            if (p3) lbuf[s3]  = KEY_OF(e3, j0 + 3);
            if (p4) lbuf[s4_] = KEY_OF(e4, j0 + 4);
            if (p5) lbuf[s5]  = KEY_OF(e5, j0 + 5);
            if (p6) lbuf[s6]  = KEY_OF(e6, j0 + 6);
            if (p7) lbuf[s7]  = KEY_OF(e7, j0 + 7);
            n = s7 + p7;
        }

        // Warp-synchronized flush keeps lanes aligned for the shfl below.
        if (__ballot_sync(0xffffffffu, n >= 9)) {
            flush16(L, lbuf, n, tau_f);
            // share tau with the partner lane (same query, other half):
            // min of the two local 16ths >= global running 16th.
            tau_f = fminf(tau_f, __shfl_xor_sync(0xffffffffu, tau_f, 1));
        }
    }

    flush16(L, lbuf, n, tau_f);   // drain

    // Merge partner halves (lane^1): min-pair vs partner's reversed sorted
    // list -> bitonic -> clean. Both lanes end with the identical top-16.
    #pragma unroll
    for (int i = 0; i < 16; ++i) {
        u64 other = __shfl_xor_sync(0xffffffffu, L[15 - i], 1);
        u64 a = L[i];
        L[i] = (a < other) ? a : other;
    }
    #pragma unroll
    for (int j = 8; j > 0; j >>= 1) {
        #pragma unroll
        for (int i = 0; i < 16; ++i) {
            int l = i ^ j;
            if (l > i) {
                u64 a = L[i], b2 = L[l];
                bool sw = a > b2;
                L[i] = sw ? b2 : a;
                L[l] = sw ? a : b2;
            }
        }
    }

    // Each partner lane writes half the 16 outputs.
    float* o = out_knn + ((long long)b * N_ + q) * K_;
    #pragma unroll
    for (int k = 0; k < 8; ++k) {
        int kk = p * 8 + k;
        o[kk] = (float)(u32)(L[kk] & 0xFFFFFFFFu);
    }
}

// ---------------------------------------------------------------------------
extern "C" void kernel_launch(void* const* d_in, const int* in_sizes, int n_in,
                              void* d_out, int out_size)
{
    const float* coords   = (const float*)d_in[0];
    const float* demands  = (const float*)d_in[1];
    const float* capacity = (const float*)d_in[2];
    const float* Wa       = (const float*)d_in[3];
    const float* ba       = (const float*)d_in[4];
    const float* W1       = (const float*)d_in[5];
    const float* b1       = (const float*)d_in[6];
    const float* W2       = (const float*)d_in[7];
    const float* b2       = (const float*)d_in[8];
    float* out = (float*)d_out;

    encode_kernel<<<dim3(N_ / 256, B_), 256>>>(coords, demands, capacity,
                                               Wa, ba, W1, b1, W2, b2, out);
    // B*N queries x 2 threads each; 128-thread blocks (64 queries/block)
    knn_kernel<<<dim3(B_ * N_ * 2 / 128), 128>>>(out + KNN_OFF);
}